// round 10
// baseline (speedup 1.0000x reference)
#include <cuda_runtime.h>
#include <math.h>

// ---------------- problem constants ----------------
#define PAD_TOK 0
#define SOS_TOK 1
#define EOS_TOK 2
#define VOCAB   50000
#define EMB     512
#define HID     1024
#define OUTC    5

// ---------------- kernel geometry ----------------
#define NBLK   128          // persistent CTAs, all co-resident
#define NTH    256
#define UNITS  8            // hidden units per CTA (warp u owns unit u)
#define KTOT   (EMB + HID)  // 1536
#define NJX    8            // x chunks -> weights in SMEM (overlap window)
#define NJH    16           // h chunks -> weights in REGS (critical path)
#define XWS_ROW 512
#define TOKCAP 2048
#define FSTR   32

typedef unsigned long long u64t;

// ---------------- global state ----------------
__device__ __align__(16) u64t g_hx[2][HID];    // ENCODER: {tag<<32 | h_bits} packets
__device__ __align__(16) float g_h[2][HID];    // DECODER: plain h (r4 protocol)
__device__ unsigned g_flags[NBLK * FSTR];      // DECODER: per-CTA flags
__device__ unsigned g_flag2[FSTR];             // DECODER: block0 -> all
__device__ __align__(16) float g_cur_emb[EMB];
__device__ int g_done;

// ---------------- sync primitives ----------------
__device__ __forceinline__ unsigned ld_acq(const unsigned* p) {
    unsigned v;
    asm volatile("ld.acquire.gpu.global.u32 %0, [%1];" : "=r"(v) : "l"(p) : "memory");
    return v;
}
__device__ __forceinline__ void st_rel(unsigned* p, unsigned v) {
    asm volatile("st.release.gpu.global.u32 [%0], %1;" :: "l"(p), "r"(v) : "memory");
}
__device__ __forceinline__ void wait_ge(const unsigned* p, unsigned tgt) {
    while ((int)(ld_acq(p) - tgt) < 0) { }
}
// SPEC-ATOMIC 8-byte packet ops: scalar b64 + relaxed.gpu = single-copy atomic
__device__ __forceinline__ void st_pkt64(u64t* p, float h, unsigned tag) {
    u64t v = ((u64t)tag << 32) | (u64t)__float_as_uint(h);
    asm volatile("st.relaxed.gpu.global.b64 [%0], %1;" :: "l"(p), "l"(v) : "memory");
}
__device__ __forceinline__ u64t ld_pkt64(const u64t* p) {
    u64t v;
    asm volatile("ld.relaxed.gpu.global.b64 %0, [%1];" : "=l"(v) : "l"(p) : "memory");
    return v;
}

// ---------------- packed dual-FMA (Blackwell f32x2) ----------------
__device__ __forceinline__ void fma2(u64t& d, u64t a, u64t b) {
    asm("fma.rn.f32x2 %0, %1, %2, %0;" : "+l"(d) : "l"(a), "l"(b));
}
__device__ __forceinline__ float f2lo(u64t v) { return __uint_as_float((unsigned)v); }
__device__ __forceinline__ float f2hi(u64t v) { return __uint_as_float((unsigned)(v >> 32)); }

// ---------------- fast activations (proven r3-r9) ----------------
__device__ __forceinline__ float fsig(float x)  { return __fdividef(1.0f, 1.0f + __expf(-x)); }
__device__ __forceinline__ float ftanh(float x) { return 1.0f - __fdividef(2.0f, __expf(2.0f * x) + 1.0f); }

// ---------------- smem plan ----------------
struct SM {
    float xh[KTOT];
    float xws[32 * XWS_ROW];   // x-part weights (64 KB)
    int   x_tok[TOKCAP];
    float pred[OUTC];
    int   nid;
    int   done;
    unsigned sbase;   // encoder packet-tag base
    unsigned fbase;   // decoder flag base
};

// ---------------- weight load: h-part -> regs, x-part -> smem ----------------
__device__ __forceinline__ void load_w(
    const float* __restrict__ Wih, const float* __restrict__ Whh,
    const float* __restrict__ bih, const float* __restrict__ bhh,
    u64t (&wr)[4][NJH], float* xws, float (&bias)[4],
    int b, int u, int lane, int tid)
{
#pragma unroll
    for (int q = 0; q < 4; q++) {
        size_t G = (size_t)q * HID + (size_t)b * UNITS + u;
        const float* rh = Whh + G * HID;
#pragma unroll
        for (int j = 0; j < NJH; j++)
            wr[q][j] = *(const u64t*)(rh + j * 64 + lane * 2);
    }
    for (int i = tid; i < 32 * (XWS_ROW / 4); i += NTH) {
        int r = i >> 7, c = i & 127;
        int q = r >> 3, uu = r & 7;
        size_t G = (size_t)q * HID + (size_t)b * UNITS + uu;
        ((float4*)(xws + (size_t)r * XWS_ROW))[c] = ((const float4*)(Wih + G * EMB))[c];
    }
    if (lane == 0) {
#pragma unroll
        for (int q = 0; q < 4; q++) {
            size_t G = (size_t)q * HID + (size_t)b * UNITS + u;
            bias[q] = bih[G] + bhh[G];
        }
    }
}

__device__ __forceinline__ void mac_x(const float* xws, const float* xh,
                                      int u, int lane, u64t (&acc)[4])
{
#pragma unroll
    for (int j = 0; j < NJX; j++) {
        u64t v = *(const u64t*)(xh + j * 64 + lane * 2);
#pragma unroll
        for (int q = 0; q < 4; q++) {
            u64t wv = *(const u64t*)(xws + (size_t)(q * 8 + u) * XWS_ROW
                                         + j * 64 + lane * 2);
            fma2(acc[q], wv, v);
        }
    }
}

__device__ __forceinline__ void mac_h(const u64t (&wr)[4][NJH], const float* xh,
                                      int lane, u64t (&acc)[4])
{
#pragma unroll
    for (int j = 0; j < NJH; j++) {
        u64t v = *(const u64t*)(xh + EMB + j * 64 + lane * 2);
        fma2(acc[0], wr[0][j], v);
        fma2(acc[1], wr[1][j], v);
        fma2(acc[2], wr[2][j], v);
        fma2(acc[3], wr[3][j], v);
    }
}

__device__ __forceinline__ float finish_unit(u64t (&acc)[4], const float (&bias)[4],
                                             int lane, float& cstate)
{
    float a0 = f2lo(acc[0]) + f2hi(acc[0]);
    float a1 = f2lo(acc[1]) + f2hi(acc[1]);
    float a2 = f2lo(acc[2]) + f2hi(acc[2]);
    float a3 = f2lo(acc[3]) + f2hi(acc[3]);
#pragma unroll
    for (int off = 16; off; off >>= 1) {
        a0 += __shfl_xor_sync(0xffffffffu, a0, off);
        a1 += __shfl_xor_sync(0xffffffffu, a1, off);
        a2 += __shfl_xor_sync(0xffffffffu, a2, off);
        a3 += __shfl_xor_sync(0xffffffffu, a3, off);
    }
    float hn = 0.0f;
    if (lane == 0) {
        float gi = a0 + bias[0], gf = a1 + bias[1];
        float gg = a2 + bias[2], go = a3 + bias[3];
        float cn = fsig(gf) * cstate + fsig(gi) * ftanh(gg);
        hn = fsig(go) * ftanh(cn);
        cstate = cn;
    }
    return hn;
}

// encoder poll: 4 packets per thread (256 threads x 4 = 1024 units)
__device__ __forceinline__ void poll4(int par, unsigned want, float* xh, int tid)
{
    const u64t* wp = &g_hx[par][tid * 4];
    u64t v0, v1, v2, v3;
    for (;;) {
        v0 = ld_pkt64(wp + 0);
        v1 = ld_pkt64(wp + 1);
        v2 = ld_pkt64(wp + 2);
        v3 = ld_pkt64(wp + 3);
        unsigned mn = min(min((unsigned)(v0 >> 32), (unsigned)(v1 >> 32)),
                          min((unsigned)(v2 >> 32), (unsigned)(v3 >> 32)));
        if ((int)(mn - want) >= 0) break;
    }
    ((float4*)(xh + EMB))[tid] = make_float4(
        __uint_as_float((unsigned)v0), __uint_as_float((unsigned)v1),
        __uint_as_float((unsigned)v2), __uint_as_float((unsigned)v3));
}

extern __shared__ __align__(16) unsigned char smem_raw[];

__global__ void __launch_bounds__(NTH, 1)
seq2seq_kernel(const int* __restrict__ x_ids, int seq,
               const float* __restrict__ emb,
               const float* __restrict__ eWih, const float* __restrict__ eWhh,
               const float* __restrict__ ebih, const float* __restrict__ ebhh,
               const float* __restrict__ dWih, const float* __restrict__ dWhh,
               const float* __restrict__ dbih, const float* __restrict__ dbhh,
               const float* __restrict__ outW, const float* __restrict__ outb,
               const int* __restrict__ maxlen_p,
               float* __restrict__ out, int out_size)
{
    SM* s = (SM*)smem_raw;
    const int tid = threadIdx.x;
    const int b = blockIdx.x;
    const int warp = tid >> 5, lane = tid & 31;   // warp == unit u

    // encoder base: max tag on own unit's packet across parities (monotonic)
    if (tid == 0) {
        unsigned t0 = (unsigned)(ld_pkt64(&g_hx[0][b * UNITS]) >> 32);
        unsigned t1 = (unsigned)(ld_pkt64(&g_hx[1][b * UNITS]) >> 32);
        s->sbase = ((int)(t0 - t1) >= 0) ? t0 : t1;
    }

    u64t wr[4][NJH];
    float bias[4] = {0.f, 0.f, 0.f, 0.f};
    load_w(eWih, eWhh, ebih, ebhh, wr, s->xws, bias, b, warp, lane, tid);
    float cstate = 0.0f;
    float h_last = 0.0f;
    for (int k = tid; k < seq && k < TOKCAP; k += NTH) s->x_tok[k] = x_ids[k];
    __syncthreads();
    const unsigned base = s->sbase;

    // publish h_0 = 0 (tag base+1, parity 0)
    if (tid < UNITS) st_pkt64(&g_hx[0][b * UNITS + tid], 0.0f, base + 1);

    if (b == 0) {                                 // init decoder feedback state
        for (int k = tid; k < out_size; k += NTH) out[k] = 0.0f;
        if (tid < EMB / 4)
            __stcg(((float4*)g_cur_emb) + tid,
                   ((const float4*)(emb + (size_t)SOS_TOK * EMB))[tid]);
        if (tid == 0) g_done = 0;
    }

    // stage x_0
    float4 epf = make_float4(0.f, 0.f, 0.f, 0.f);
    if (tid < 128 && seq > 0) {
        int tok0 = s->x_tok[0];
        epf = ((const float4*)(emb + (size_t)tok0 * EMB))[tid];
        ((float4*)s->xh)[tid] = epf;
    }
    __syncthreads();

    // ---- encoder: single-round-trip tagged exchange ----
    for (int t = 0; t < seq; t++) {
        u64t acc[4] = {0ull, 0ull, 0ull, 0ull};
        mac_x(s->xws, s->xh, warp, lane, acc);        // overlaps producers' publishes

        if (tid < 128 && t + 1 < seq) {               // prefetch next emb row
            int tk = (t + 1 < TOKCAP) ? s->x_tok[t + 1] : __ldg(&x_ids[t + 1]);
            epf = ((const float4*)(emb + (size_t)tk * EMB))[tid];
        }
        poll4(t & 1, base + 1 + (unsigned)t, s->xh, tid);
        __syncthreads();                              // h_t staged; mac_x done in all warps

        mac_h(wr, s->xh, lane, acc);                  // critical path: regs only
        float hn = finish_unit(acc, bias, lane, cstate);
        if (lane == 0) {
            h_last = hn;
            st_pkt64(&g_hx[(t + 1) & 1][b * UNITS + warp], hn, base + 2 + (unsigned)t);
        }
        if (tid < 128 && t + 1 < seq) ((float4*)s->xh)[tid] = epf;   // stage x_{t+1}
        __syncthreads();                              // gate xh reuse for next iteration
    }

    // ---- bridge: republish h_seq in decoder (flag) format ----
    if (tid == 0) s->fbase = __ldcg(&g_flags[b * FSTR]);
    __syncthreads();
    const unsigned F0 = s->fbase;
    if (lane == 0) __stcg(&g_h[0][b * UNITS + warp], h_last);
    __syncthreads();
    if (tid == 0) st_rel(&g_flags[b * FSTR], F0 + 1);
    if (b == 0 && tid == 0) st_rel(&g_flag2[0], F0 + 1);

    // ---- decoder weights ----
    load_w(dWih, dWhh, dbih, dbhh, wr, s->xws, bias, b, warp, lane, tid);
    const int maxlen = *maxlen_p;
    __syncthreads();

    // ---- decoder: r4/r9-proven flag protocol ----
    for (int d = 0; d < maxlen; d++) {
        if (tid == 0) {
            wait_ge(&g_flag2[0], F0 + 1 + (unsigned)d);
            s->done = __ldcg(&g_done);
        }
        __syncthreads();
        if (s->done) break;

        int p = d & 1;
        if (tid < 128) {
            ((float4*)s->xh)[tid] = __ldcg(((const float4*)g_cur_emb) + tid);
            wait_ge(&g_flags[tid * FSTR], F0 + 1 + (unsigned)d);
            const float4* hp = (const float4*)(g_h[p] + tid * UNITS);
            float4 v0 = __ldcg(hp), v1 = __ldcg(hp + 1);
            ((float4*)(s->xh + EMB))[tid * 2 + 0] = v0;
            ((float4*)(s->xh + EMB))[tid * 2 + 1] = v1;
        }
        __syncthreads();

        u64t acc[4] = {0ull, 0ull, 0ull, 0ull};
        mac_x(s->xws, s->xh, warp, lane, acc);
        mac_h(wr, s->xh, lane, acc);
        float hn = finish_unit(acc, bias, lane, cstate);
        if (lane == 0) __stcg(&g_h[p ^ 1][b * UNITS + warp], hn);
        __syncthreads();
        if (tid == 0) st_rel(&g_flags[b * FSTR], F0 + 2 + (unsigned)d);

        if (b == 0) {   // projection (reads GLOBAL g_h), greedy feedback
            if (tid < 128) wait_ge(&g_flags[tid * FSTR], F0 + 2 + (unsigned)d);
            __syncthreads();
            if (warp < OUTC) {
                const float* hrow = g_h[p ^ 1];
                float a = 0.0f;
                for (int k = lane; k < HID; k += 32)
                    a += __ldcg(hrow + k) * outW[(size_t)warp * HID + k];
#pragma unroll
                for (int off = 16; off; off >>= 1)
                    a += __shfl_xor_sync(0xffffffffu, a, off);
                if (lane == 0) s->pred[warp] = a + outb[warp];
            }
            __syncthreads();
            if (tid == 0) {
                for (int o = 0; o < OUTC; o++) out[d * OUTC + o] = s->pred[o];
                if (maxlen * OUTC + d < out_size) out[maxlen * OUTC + d] = 1.0f;
                float r = rintf(s->pred[0]);          // half-to-even like jnp.round
                r = fminf(fmaxf(r, 0.0f), (float)(VOCAB - 1));
                int nid = (int)r;
                s->nid = nid;
                if (nid == EOS_TOK) g_done = 1;
            }
            __syncthreads();
            int nid = s->nid;
            float sc = (nid != PAD_TOK) ? 1.0f : 0.0f;
            for (int k = tid; k < EMB; k += NTH)
                __stcg(&g_cur_emb[k], emb[(size_t)nid * EMB + k] * sc);
            __syncthreads();
            if (tid == 0) st_rel(&g_flag2[0], F0 + 2 + (unsigned)d);
        }
        __syncthreads();
    }
}

extern "C" void kernel_launch(void* const* d_in, const int* in_sizes, int n_in,
                              void* d_out, int out_size)
{
    const int*   x    = (const int*)  d_in[0];
    const float* emb  = (const float*)d_in[1];
    const float* eWih = (const float*)d_in[2];
    const float* eWhh = (const float*)d_in[3];
    const float* ebih = (const float*)d_in[4];
    const float* ebhh = (const float*)d_in[5];
    const float* dWih = (const float*)d_in[6];
    const float* dWhh = (const float*)d_in[7];
    const float* dbih = (const float*)d_in[8];
    const float* dbhh = (const float*)d_in[9];
    const float* outW = (const float*)d_in[10];
    const float* outb = (const float*)d_in[11];
    const int*   mlp  = (const int*)  d_in[12];
    int seq = in_sizes[0];

    int smem_bytes = (int)sizeof(SM);
    cudaFuncSetAttribute(seq2seq_kernel,
                         cudaFuncAttributeMaxDynamicSharedMemorySize, smem_bytes);

    seq2seq_kernel<<<NBLK, NTH, smem_bytes>>>(
        x, seq, emb, eWih, eWhh, ebih, ebhh,
        dWih, dWhh, dbih, dbhh, outW, outb, mlp,
        (float*)d_out, out_size);
}

// round 12
// speedup vs baseline: 1.0229x; 1.0229x over previous
#include <cuda_runtime.h>
#include <math.h>

// ---------------- problem constants ----------------
#define PAD_TOK 0
#define SOS_TOK 1
#define EOS_TOK 2
#define VOCAB   50000
#define EMB     512
#define HID     1024
#define OUTC    5
#define GROWS   (4 * HID)     // 4096 fused gate rows
#define TMAX    2048

// ---------------- kernel geometry ----------------
#define NBLK   128
#define NTH    256
#define UNITS  8              // warp u owns unit u
#define KTOT   (EMB + HID)
#define NJX    8              // x chunks (decoder mac_x, smem weights)
#define NJH    16             // h chunks (register weights)
#define XWS_ROW 512
#define FSTR   32

typedef unsigned long long u64t;

// ---------------- global state ----------------
__device__ unsigned g_flags[NBLK * FSTR];
__device__ unsigned g_flag2[FSTR];
__device__ __align__(16) float g_h[2][HID];
__device__ __align__(16) float g_cur_emb[EMB];
__device__ int g_done;
__device__ float g_gx[(size_t)GROWS * TMAX];   // precomputed Wih @ emb[x_t] (32 MB)

// ---------------- sync primitives ----------------
__device__ __forceinline__ unsigned ld_acq(const unsigned* p) {
    unsigned v;
    asm volatile("ld.acquire.gpu.global.u32 %0, [%1];" : "=r"(v) : "l"(p) : "memory");
    return v;
}
__device__ __forceinline__ void st_rel(unsigned* p, unsigned v) {
    asm volatile("st.release.gpu.global.u32 [%0], %1;" :: "l"(p), "r"(v) : "memory");
}
__device__ __forceinline__ void wait_ge(const unsigned* p, unsigned tgt) {
    while ((int)(ld_acq(p) - tgt) < 0) { }
}

// ---------------- packed dual-FMA ----------------
__device__ __forceinline__ void fma2(u64t& d, u64t a, u64t b) {
    asm("fma.rn.f32x2 %0, %1, %2, %0;" : "+l"(d) : "l"(a), "l"(b));
}
__device__ __forceinline__ float f2lo(u64t v) { return __uint_as_float((unsigned)v); }
__device__ __forceinline__ float f2hi(u64t v) { return __uint_as_float((unsigned)(v >> 32)); }

__device__ __forceinline__ float fsig(float x)  { return __fdividef(1.0f, 1.0f + __expf(-x)); }
__device__ __forceinline__ float ftanh(float x) { return 1.0f - __fdividef(2.0f, __expf(2.0f * x) + 1.0f); }

// ---------------- smem plan ----------------
struct SM {
    float xh[KTOT];
    float xws[32 * XWS_ROW];   // x weights (decoder only)
    float pred[OUTC];
    int   nid;
    int   done;
    unsigned sbase;
};

// ============================================================
// Kernel 1: gx precompute — C[G][t] = Wih[G,:] . emb[x_t,:]
// tile 32 rows x 32 t, k-blocked 64; 256 threads
// ============================================================
__global__ void __launch_bounds__(256, 4)
gx_kernel(const int* __restrict__ x_ids, int seq,
          const float* __restrict__ emb, const float* __restrict__ Wih)
{
    __shared__ float At[32][65];
    __shared__ float Bt[64][33];
    __shared__ int   toks[32];
    const int tid = threadIdx.x;
    const int r0 = blockIdx.x * 32;
    const int t0 = blockIdx.y * 32;

    if (tid < 32) {
        int t = t0 + tid;
        toks[tid] = (t < seq) ? x_ids[t] : PAD_TOK;   // emb[PAD] row is zero
    }
    __syncthreads();

    float acc0 = 0.f, acc1 = 0.f, acc2 = 0.f, acc3 = 0.f;
    const int rr = tid >> 3;            // 0..31
    const int tc = (tid & 7) * 4;       // 0..28

    for (int kb = 0; kb < EMB; kb += 64) {
#pragma unroll
        for (int j = 0; j < 8; j++) {   // stage A and B (2048 floats each)
            int lin = tid + 256 * j;
            int ar = lin >> 6, ak = lin & 63;
            At[ar][ak] = Wih[(size_t)(r0 + ar) * EMB + kb + ak];
            Bt[ak][ar] = emb[(size_t)toks[ar] * EMB + kb + ak];
        }
        __syncthreads();
#pragma unroll
        for (int k = 0; k < 64; k++) {
            float a = At[rr][k];
            acc0 = fmaf(a, Bt[k][tc + 0], acc0);
            acc1 = fmaf(a, Bt[k][tc + 1], acc1);
            acc2 = fmaf(a, Bt[k][tc + 2], acc2);
            acc3 = fmaf(a, Bt[k][tc + 3], acc3);
        }
        __syncthreads();
    }
    float* cp = &g_gx[(size_t)(r0 + rr) * TMAX + t0 + tc];
    cp[0] = acc0; cp[1] = acc1; cp[2] = acc2; cp[3] = acc3;
}

// ---------------- weight load: h -> regs, x -> smem (optional) -------------
// BIAS FIX: every lane loads all 4 biases (distributed finish reads
// bias[lane&3] on lanes 0-3; r11 loaded them on lane 0 only -> gates f,g,o
// silently lost their bias).
__device__ __forceinline__ void load_w(
    const float* __restrict__ Wih, const float* __restrict__ Whh,
    const float* __restrict__ bih, const float* __restrict__ bhh,
    u64t (&wr)[4][NJH], float* xws, float (&bias)[4],
    int b, int u, int lane, int tid, bool want_x)
{
#pragma unroll
    for (int q = 0; q < 4; q++) {
        size_t G = (size_t)q * HID + (size_t)b * UNITS + u;
        const float* rh = Whh + G * HID;
#pragma unroll
        for (int j = 0; j < NJH; j++)
            wr[q][j] = *(const u64t*)(rh + j * 64 + lane * 2);
    }
    if (want_x) {
        for (int i = tid; i < 32 * (XWS_ROW / 4); i += NTH) {
            int r = i >> 7, c = i & 127;
            int q = r >> 3, uu = r & 7;
            size_t G = (size_t)q * HID + (size_t)b * UNITS + uu;
            ((float4*)(xws + (size_t)r * XWS_ROW))[c] = ((const float4*)(Wih + G * EMB))[c];
        }
    }
#pragma unroll
    for (int q = 0; q < 4; q++) {
        size_t G = (size_t)q * HID + (size_t)b * UNITS + u;
        bias[q] = bih[G] + bhh[G];
    }
}

__device__ __forceinline__ void mac_x(const float* xws, const float* xh,
                                      int u, int lane, u64t (&acc)[4])
{
#pragma unroll
    for (int j = 0; j < NJX; j++) {
        u64t v = *(const u64t*)(xh + j * 64 + lane * 2);
#pragma unroll
        for (int q = 0; q < 4; q++) {
            u64t wv = *(const u64t*)(xws + (size_t)(q * 8 + u) * XWS_ROW
                                         + j * 64 + lane * 2);
            fma2(acc[q], wv, v);
        }
    }
}

__device__ __forceinline__ void mac_h(const u64t (&wr)[4][NJH], const float* xh,
                                      int lane, u64t (&acc)[4])
{
#pragma unroll
    for (int j = 0; j < NJH; j++) {
        u64t v = *(const u64t*)(xh + EMB + j * 64 + lane * 2);
        fma2(acc[0], wr[0][j], v);
        fma2(acc[1], wr[1][j], v);
        fma2(acc[2], wr[2][j], v);
        fma2(acc[3], wr[3][j], v);
    }
}

// distributed finish: butterfly routes gate-k total to lane k (mod 4);
// parallel activations; lane0 combines. gx = precomputed x-contribution
// for gate (lane&3) of this warp's unit (0 where unused).
__device__ __forceinline__ float finish_unit(u64t (&acc)[4], const float (&bias)[4],
                                             float gx, int lane, float& cstate)
{
    float a0 = f2lo(acc[0]) + f2hi(acc[0]);
    float a1 = f2lo(acc[1]) + f2hi(acc[1]);
    float a2 = f2lo(acc[2]) + f2hi(acc[2]);
    float a3 = f2lo(acc[3]) + f2hi(acc[3]);
#pragma unroll
    for (int off = 16; off >= 4; off >>= 1) {
        a0 += __shfl_xor_sync(0xffffffffu, a0, off);
        a1 += __shfl_xor_sync(0xffffffffu, a1, off);
        a2 += __shfl_xor_sync(0xffffffffu, a2, off);
        a3 += __shfl_xor_sync(0xffffffffu, a3, off);
    }
    // offset 2: route (a0,a2) and (a1,a3) by bit1
    float t02 = (lane & 2) ? a2 : a0;
    float o02 = (lane & 2) ? a0 : a2;
    t02 += __shfl_xor_sync(0xffffffffu, o02, 2);
    float t13 = (lane & 2) ? a3 : a1;
    float o13 = (lane & 2) ? a1 : a3;
    t13 += __shfl_xor_sync(0xffffffffu, o13, 2);
    // offset 1: route by bit0 -> lane k (mod 4) holds gate-k total
    float v = (lane & 1) ? t13 : t02;
    float o = (lane & 1) ? t02 : t13;
    v += __shfl_xor_sync(0xffffffffu, o, 1);

    float bsel = (lane & 2) ? ((lane & 1) ? bias[3] : bias[2])
                            : ((lane & 1) ? bias[1] : bias[0]);
    float g = v + bsel + gx;
    // lanes 0,1,3: sigmoid; lane 2: tanh = 2*sig(2g)-1 (one MUFU chain)
    bool is_g = ((lane & 3) == 2);
    float m = is_g ? 2.0f : 1.0f;
    float c0 = is_g ? -1.0f : 0.0f;
    float act = fmaf(m, fsig(m * g), c0);

    float si = act;                                   // lane0: sig(i)
    float sf = __shfl_sync(0xffffffffu, act, 1);      // sig(f)
    float tg = __shfl_sync(0xffffffffu, act, 2);      // tanh(g)
    float so = __shfl_sync(0xffffffffu, act, 3);      // sig(o)
    float hn = 0.0f;
    if (lane == 0) {
        float cn = sf * cstate + si * tg;
        hn = so * ftanh(cn);
        cstate = cn;
    }
    return hn;
}

extern __shared__ __align__(16) unsigned char smem_raw[];

__global__ void __launch_bounds__(NTH, 1)
seq2seq_kernel(const int* __restrict__ x_ids, int seq,
               const float* __restrict__ emb,
               const float* __restrict__ eWih, const float* __restrict__ eWhh,
               const float* __restrict__ ebih, const float* __restrict__ ebhh,
               const float* __restrict__ dWih, const float* __restrict__ dWhh,
               const float* __restrict__ dbih, const float* __restrict__ dbhh,
               const float* __restrict__ outW, const float* __restrict__ outb,
               const int* __restrict__ maxlen_p,
               float* __restrict__ out, int out_size)
{
    SM* s = (SM*)smem_raw;
    const int tid = threadIdx.x;
    const int b = blockIdx.x;
    const int warp = tid >> 5, lane = tid & 31;   // warp == unit u

    if (tid == 0) s->sbase = __ldcg(&g_flags[b * FSTR]);

    u64t wr[4][NJH];
    float bias[4] = {0.f, 0.f, 0.f, 0.f};
    load_w(eWih, eWhh, ebih, ebhh, wr, s->xws, bias, b, warp, lane, tid, false);
    float cstate = 0.0f;
    __syncthreads();
    const unsigned base = s->sbase;

    if (tid == 0) {                                 // publish h_0 = 0
        float4 z = make_float4(0.f, 0.f, 0.f, 0.f);
        float4* dst = (float4*)(g_h[0] + b * UNITS);
        __stcg(dst, z); __stcg(dst + 1, z);
        st_rel(&g_flags[b * FSTR], base + 1);
    }
    if (b == 0) {                                   // publish emb_0 / done_0
        for (int k = tid; k < out_size; k += NTH) out[k] = 0.0f;
        if (tid < EMB / 4)
            __stcg(((float4*)g_cur_emb) + tid,
                   ((const float4*)(emb + (size_t)SOS_TOK * EMB))[tid]);
        if (tid == 0) g_done = 0;
        __syncthreads();
        if (tid == 0) st_rel(&g_flag2[0], base + 1 + (unsigned)seq);
    }

    // gx pointer for this warp's unit, gate = lane (lanes 0..3)
    const float* gxp = (lane < 4)
        ? &g_gx[(size_t)(lane * HID + b * UNITS + warp) * TMAX] : (const float*)0;

    // ---- encoder: no x-MAC, no emb traffic — pure h recurrence ----
    for (int t = 0; t < seq; t++) {
        float gx = (lane < 4) ? __ldcg(gxp + t) : 0.0f;   // issued early, hidden

        if (tid < 128) {
            wait_ge(&g_flags[tid * FSTR], base + 1 + (unsigned)t);
            const float4* hp = (const float4*)(g_h[t & 1] + tid * UNITS);
            float4 v0 = __ldcg(hp), v1 = __ldcg(hp + 1);
            ((float4*)(s->xh + EMB))[tid * 2 + 0] = v0;
            ((float4*)(s->xh + EMB))[tid * 2 + 1] = v1;
        }
        __syncthreads();

        u64t acc[4] = {0ull, 0ull, 0ull, 0ull};
        mac_h(wr, s->xh, lane, acc);
        float hn = finish_unit(acc, bias, gx, lane, cstate);
        if (lane == 0) __stcg(&g_h[(t + 1) & 1][b * UNITS + warp], hn);
        __syncthreads();
        if (tid == 0) st_rel(&g_flags[b * FSTR], base + 2 + (unsigned)t);
    }

    // ---- decoder weights (x weights to smem now) ----
    load_w(dWih, dWhh, dbih, dbhh, wr, s->xws, bias, b, warp, lane, tid, true);
    const int maxlen = *maxlen_p;
    __syncthreads();

    // ---- decoder: r9-proven protocol ----
    for (int d = 0; d < maxlen; d++) {
        const unsigned eh = base + 1 + (unsigned)(seq + d);
        if (tid == 0) {
            wait_ge(&g_flag2[0], eh);
            s->done = __ldcg(&g_done);
        }
        __syncthreads();
        if (s->done) break;

        int p = (seq + d) & 1;
        if (tid < 128) {
            ((float4*)s->xh)[tid] = __ldcg(((const float4*)g_cur_emb) + tid);
            wait_ge(&g_flags[tid * FSTR], eh);
            const float4* hp = (const float4*)(g_h[p] + tid * UNITS);
            float4 v0 = __ldcg(hp), v1 = __ldcg(hp + 1);
            ((float4*)(s->xh + EMB))[tid * 2 + 0] = v0;
            ((float4*)(s->xh + EMB))[tid * 2 + 1] = v1;
        }
        __syncthreads();

        u64t acc[4] = {0ull, 0ull, 0ull, 0ull};
        mac_x(s->xws, s->xh, warp, lane, acc);
        mac_h(wr, s->xh, lane, acc);
        float hn = finish_unit(acc, bias, 0.0f, lane, cstate);
        if (lane == 0) __stcg(&g_h[p ^ 1][b * UNITS + warp], hn);
        __syncthreads();
        if (tid == 0) st_rel(&g_flags[b * FSTR], eh + 1);

        if (b == 0) {
            if (tid < 128) wait_ge(&g_flags[tid * FSTR], eh + 1);
            __syncthreads();
            if (warp < OUTC) {
                const float* hrow = g_h[p ^ 1];
                float a = 0.0f;
                for (int k = lane; k < HID; k += 32)
                    a += __ldcg(hrow + k) * outW[(size_t)warp * HID + k];
#pragma unroll
                for (int off = 16; off; off >>= 1)
                    a += __shfl_xor_sync(0xffffffffu, a, off);
                if (lane == 0) s->pred[warp] = a + outb[warp];
            }
            __syncthreads();
            if (tid == 0) {
                for (int o = 0; o < OUTC; o++) out[d * OUTC + o] = s->pred[o];
                if (maxlen * OUTC + d < out_size) out[maxlen * OUTC + d] = 1.0f;
                float r = rintf(s->pred[0]);              // half-to-even like jnp.round
                r = fminf(fmaxf(r, 0.0f), (float)(VOCAB - 1));
                int nid = (int)r;
                s->nid = nid;
                if (nid == EOS_TOK) g_done = 1;
            }
            __syncthreads();
            int nid = s->nid;
            float sc = (nid != PAD_TOK) ? 1.0f : 0.0f;
            for (int k = tid; k < EMB; k += NTH)
                __stcg(&g_cur_emb[k], emb[(size_t)nid * EMB + k] * sc);
            __syncthreads();
            if (tid == 0) st_rel(&g_flag2[0], eh + 1);
        }
        __syncthreads();
    }
}

extern "C" void kernel_launch(void* const* d_in, const int* in_sizes, int n_in,
                              void* d_out, int out_size)
{
    const int*   x    = (const int*)  d_in[0];
    const float* emb  = (const float*)d_in[1];
    const float* eWih = (const float*)d_in[2];
    const float* eWhh = (const float*)d_in[3];
    const float* ebih = (const float*)d_in[4];
    const float* ebhh = (const float*)d_in[5];
    const float* dWih = (const float*)d_in[6];
    const float* dWhh = (const float*)d_in[7];
    const float* dbih = (const float*)d_in[8];
    const float* dbhh = (const float*)d_in[9];
    const float* outW = (const float*)d_in[10];
    const float* outb = (const float*)d_in[11];
    const int*   mlp  = (const int*)  d_in[12];
    int seq = in_sizes[0];
    if (seq > TMAX) seq = TMAX;

    // phase 1: full-grid GEMM for gate x-contributions
    dim3 ggrid(GROWS / 32, (seq + 31) / 32);
    gx_kernel<<<ggrid, 256>>>(x, seq, emb, eWih);

    // phase 2: persistent recurrence
    int smem_bytes = (int)sizeof(SM);
    cudaFuncSetAttribute(seq2seq_kernel,
                         cudaFuncAttributeMaxDynamicSharedMemorySize, smem_bytes);
    seq2seq_kernel<<<NBLK, NTH, smem_bytes>>>(
        x, seq, emb, eWih, eWhh, ebih, ebhh,
        dWih, dWhh, dbih, dbhh, outW, outb, mlp,
        (float*)d_out, out_size);
}

// round 14
// speedup vs baseline: 1.1591x; 1.1333x over previous
#include <cuda_runtime.h>
#include <math.h>

// ---------------- problem constants ----------------
#define PAD_TOK 0
#define SOS_TOK 1
#define EOS_TOK 2
#define VOCAB   50000
#define EMB     512
#define HID     1024
#define OUTC    5

// ---------------- kernel geometry ----------------
#define NBLK   128          // persistent CTAs, all co-resident
#define NTH    256
#define UNITS  8            // hidden units per CTA (warp u owns unit u)
#define KTOT   (EMB + HID)  // 1536
#define NJX    8            // x chunks -> weights in SMEM (overlap window)
#define NJH    16           // h chunks -> weights in REGS (critical path)
#define XWS_ROW 512
#define TOKCAP 2048
#define FSTR   32

typedef unsigned long long u64t;

// ---------------- global state (r9-proven protocol) ----------------
__device__ unsigned g_flags[NBLK * FSTR];   // per-CTA h epoch flags
__device__ unsigned g_flag2[FSTR];          // block0 -> all (emb/done epoch)
__device__ __align__(16) float g_h[2][HID];
__device__ __align__(16) float g_cur_emb[EMB];
__device__ int g_done;

// ---------------- sync primitives ----------------
__device__ __forceinline__ unsigned ld_acq(const unsigned* p) {
    unsigned v;
    asm volatile("ld.acquire.gpu.global.u32 %0, [%1];" : "=r"(v) : "l"(p) : "memory");
    return v;
}
__device__ __forceinline__ void st_rel(unsigned* p, unsigned v) {
    asm volatile("st.release.gpu.global.u32 [%0], %1;" :: "l"(p), "r"(v) : "memory");
}
__device__ __forceinline__ void wait_ge(const unsigned* p, unsigned tgt) {
    while ((int)(ld_acq(p) - tgt) < 0) { }
}

// ---------------- packed dual-FMA (Blackwell f32x2) ----------------
__device__ __forceinline__ void fma2(u64t& d, u64t a, u64t b) {
    asm("fma.rn.f32x2 %0, %1, %2, %0;" : "+l"(d) : "l"(a), "l"(b));
}
__device__ __forceinline__ float f2lo(u64t v) { return __uint_as_float((unsigned)v); }
__device__ __forceinline__ float f2hi(u64t v) { return __uint_as_float((unsigned)(v >> 32)); }

__device__ __forceinline__ float fsig(float x)  { return __fdividef(1.0f, 1.0f + __expf(-x)); }
__device__ __forceinline__ float ftanh(float x) { return 1.0f - __fdividef(2.0f, __expf(2.0f * x) + 1.0f); }

// ---------------- smem plan ----------------
struct SM {
    float xh[KTOT];
    float xws[32 * XWS_ROW];   // x-part weights (64 KB)
    int   x_tok[TOKCAP];
    float pred[OUTC];
    int   nid;
    int   done;
    unsigned sbase;
};

// ---------------- weight load: h-part -> regs, x-part -> smem ----------------
// ALL lanes load all 4 biases (distributed finish reads bias[lane&3]).
__device__ __forceinline__ void load_w(
    const float* __restrict__ Wih, const float* __restrict__ Whh,
    const float* __restrict__ bih, const float* __restrict__ bhh,
    u64t (&wr)[4][NJH], float* xws, float (&bias)[4],
    int b, int u, int lane, int tid)
{
#pragma unroll
    for (int q = 0; q < 4; q++) {
        size_t G = (size_t)q * HID + (size_t)b * UNITS + u;
        const float* rh = Whh + G * HID;
#pragma unroll
        for (int j = 0; j < NJH; j++)
            wr[q][j] = *(const u64t*)(rh + j * 64 + lane * 2);
    }
    for (int i = tid; i < 32 * (XWS_ROW / 4); i += NTH) {
        int r = i >> 7, c = i & 127;
        int q = r >> 3, uu = r & 7;
        size_t G = (size_t)q * HID + (size_t)b * UNITS + uu;
        ((float4*)(xws + (size_t)r * XWS_ROW))[c] = ((const float4*)(Wih + G * EMB))[c];
    }
#pragma unroll
    for (int q = 0; q < 4; q++) {
        size_t G = (size_t)q * HID + (size_t)b * UNITS + u;
        bias[q] = bih[G] + bhh[G];
    }
}

__device__ __forceinline__ void mac_x(const float* xws, const float* xh,
                                      int u, int lane, u64t (&acc)[4])
{
#pragma unroll
    for (int j = 0; j < NJX; j++) {
        u64t v = *(const u64t*)(xh + j * 64 + lane * 2);
#pragma unroll
        for (int q = 0; q < 4; q++) {
            u64t wv = *(const u64t*)(xws + (size_t)(q * 8 + u) * XWS_ROW
                                         + j * 64 + lane * 2);
            fma2(acc[q], wv, v);
        }
    }
}

__device__ __forceinline__ void mac_h(const u64t (&wr)[4][NJH], const float* xh,
                                      int lane, u64t (&acc)[4])
{
#pragma unroll
    for (int j = 0; j < NJH; j++) {
        u64t v = *(const u64t*)(xh + EMB + j * 64 + lane * 2);
        fma2(acc[0], wr[0][j], v);
        fma2(acc[1], wr[1][j], v);
        fma2(acc[2], wr[2][j], v);
        fma2(acc[3], wr[3][j], v);
    }
}

// distributed finish (validated in r12): butterfly routes gate-k total to
// lane k (mod 4); parallel activations; lane0 combines.
__device__ __forceinline__ float finish_unit(u64t (&acc)[4], const float (&bias)[4],
                                             int lane, float& cstate)
{
    float a0 = f2lo(acc[0]) + f2hi(acc[0]);
    float a1 = f2lo(acc[1]) + f2hi(acc[1]);
    float a2 = f2lo(acc[2]) + f2hi(acc[2]);
    float a3 = f2lo(acc[3]) + f2hi(acc[3]);
#pragma unroll
    for (int off = 16; off >= 4; off >>= 1) {
        a0 += __shfl_xor_sync(0xffffffffu, a0, off);
        a1 += __shfl_xor_sync(0xffffffffu, a1, off);
        a2 += __shfl_xor_sync(0xffffffffu, a2, off);
        a3 += __shfl_xor_sync(0xffffffffu, a3, off);
    }
    float t02 = (lane & 2) ? a2 : a0;
    float o02 = (lane & 2) ? a0 : a2;
    t02 += __shfl_xor_sync(0xffffffffu, o02, 2);
    float t13 = (lane & 2) ? a3 : a1;
    float o13 = (lane & 2) ? a1 : a3;
    t13 += __shfl_xor_sync(0xffffffffu, o13, 2);
    float v = (lane & 1) ? t13 : t02;
    float o = (lane & 1) ? t02 : t13;
    v += __shfl_xor_sync(0xffffffffu, o, 1);

    float bsel = (lane & 2) ? ((lane & 1) ? bias[3] : bias[2])
                            : ((lane & 1) ? bias[1] : bias[0]);
    float g = v + bsel;
    bool is_g = ((lane & 3) == 2);
    float m = is_g ? 2.0f : 1.0f;
    float c0 = is_g ? -1.0f : 0.0f;
    float act = fmaf(m, fsig(m * g), c0);     // lanes 0,1,3: sig; lane 2: tanh

    float si = act;
    float sf = __shfl_sync(0xffffffffu, act, 1);
    float tg = __shfl_sync(0xffffffffu, act, 2);
    float so = __shfl_sync(0xffffffffu, act, 3);
    float hn = 0.0f;
    if (lane == 0) {
        float cn = sf * cstate + si * tg;
        hn = so * ftanh(cn);
        cstate = cn;
    }
    return hn;
}

extern __shared__ __align__(16) unsigned char smem_raw[];

__global__ void __launch_bounds__(NTH, 1)
seq2seq_kernel(const int* __restrict__ x_ids, int seq,
               const float* __restrict__ emb,
               const float* __restrict__ eWih, const float* __restrict__ eWhh,
               const float* __restrict__ ebih, const float* __restrict__ ebhh,
               const float* __restrict__ dWih, const float* __restrict__ dWhh,
               const float* __restrict__ dbih, const float* __restrict__ dbhh,
               const float* __restrict__ outW, const float* __restrict__ outb,
               const int* __restrict__ maxlen_p,
               float* __restrict__ out, int out_size)
{
    SM* s = (SM*)smem_raw;
    const int tid = threadIdx.x;
    const int b = blockIdx.x;
    const int warp = tid >> 5, lane = tid & 31;   // warp == unit u

    // flag base (own flag: exact, uniform across CTAs at replay boundaries)
    if (tid == 0) s->sbase = __ldcg(&g_flags[b * FSTR]);

    u64t wr[4][NJH];
    float bias[4];
    load_w(eWih, eWhh, ebih, ebhh, wr, s->xws, bias, b, warp, lane, tid);
    float cstate = 0.0f;
    for (int k = tid; k < seq && k < TOKCAP; k += NTH) s->x_tok[k] = x_ids[k];
    __syncthreads();
    const unsigned base = s->sbase;

    if (tid == 0) {                                 // publish h_0 = 0
        float4 z = make_float4(0.f, 0.f, 0.f, 0.f);
        float4* dst = (float4*)(g_h[0] + b * UNITS);
        __stcg(dst, z); __stcg(dst + 1, z);
        st_rel(&g_flags[b * FSTR], base + 1);
    }
    if (b == 0) {                                   // publish emb_0 / done_0
        for (int k = tid; k < out_size; k += NTH) out[k] = 0.0f;
        if (tid < EMB / 4)
            __stcg(((float4*)g_cur_emb) + tid,
                   ((const float4*)(emb + (size_t)SOS_TOK * EMB))[tid]);
        if (tid == 0) g_done = 0;
        __syncthreads();
        if (tid == 0) st_rel(&g_flag2[0], base + 1 + (unsigned)seq);
    }

    // x-part of xh for t=0
    float4 epf = make_float4(0.f, 0.f, 0.f, 0.f);
    if (tid < 128 && seq > 0) {
        int tok0 = s->x_tok[0];
        epf = ((const float4*)(emb + (size_t)tok0 * EMB))[tid];
        ((float4*)s->xh)[tid] = epf;
    }
    __syncthreads();

    // ---- encoder (r9 protocol; x-MAC from smem overlaps the wait) ----
    for (int t = 0; t < seq; t++) {
        u64t acc[4] = {0ull, 0ull, 0ull, 0ull};
        mac_x(s->xws, s->xh, warp, lane, acc);           // overlap window work

        if (tid < 128) {
            if (t + 1 < seq) {                            // prefetch next emb row
                int tk = (t + 1 < TOKCAP) ? s->x_tok[t + 1] : __ldg(&x_ids[t + 1]);
                epf = ((const float4*)(emb + (size_t)tk * EMB))[tid];
            }
            wait_ge(&g_flags[tid * FSTR], base + 1 + (unsigned)t);
            const float4* hp = (const float4*)(g_h[t & 1] + tid * UNITS);
            float4 v0 = __ldcg(hp), v1 = __ldcg(hp + 1);
            ((float4*)(s->xh + EMB))[tid * 2 + 0] = v0;
            ((float4*)(s->xh + EMB))[tid * 2 + 1] = v1;
        }
        __syncthreads();

        mac_h(wr, s->xh, lane, acc);                      // critical path: regs only
        float hn = finish_unit(acc, bias, lane, cstate);

        if (tid < 128) ((float4*)s->xh)[tid] = epf;       // stage x_{t+1}
        if (lane == 0) __stcg(&g_h[(t + 1) & 1][b * UNITS + warp], hn);
        __syncthreads();
        if (tid == 0) st_rel(&g_flags[b * FSTR], base + 2 + (unsigned)t);
    }

    // ---- decoder weights ----
    load_w(dWih, dWhh, dbih, dbhh, wr, s->xws, bias, b, warp, lane, tid);
    const int maxlen = *maxlen_p;
    __syncthreads();

    // ---- decoder (r9 protocol verbatim) ----
    for (int d = 0; d < maxlen; d++) {
        const unsigned eh = base + 1 + (unsigned)(seq + d);
        if (tid == 0) {
            wait_ge(&g_flag2[0], eh);
            s->done = __ldcg(&g_done);
        }
        __syncthreads();
        if (s->done) break;

        int p = (seq + d) & 1;
        if (tid < 128) {
            ((float4*)s->xh)[tid] = __ldcg(((const float4*)g_cur_emb) + tid);
            wait_ge(&g_flags[tid * FSTR], eh);
            const float4* hp = (const float4*)(g_h[p] + tid * UNITS);
            float4 v0 = __ldcg(hp), v1 = __ldcg(hp + 1);
            ((float4*)(s->xh + EMB))[tid * 2 + 0] = v0;
            ((float4*)(s->xh + EMB))[tid * 2 + 1] = v1;
        }
        __syncthreads();

        u64t acc[4] = {0ull, 0ull, 0ull, 0ull};
        mac_x(s->xws, s->xh, warp, lane, acc);
        mac_h(wr, s->xh, lane, acc);
        float hn = finish_unit(acc, bias, lane, cstate);
        if (lane == 0) __stcg(&g_h[p ^ 1][b * UNITS + warp], hn);
        __syncthreads();
        if (tid == 0) st_rel(&g_flags[b * FSTR], eh + 1);

        // block 0: projection (reads GLOBAL g_h), greedy feedback
        if (b == 0) {
            if (tid < 128) wait_ge(&g_flags[tid * FSTR], eh + 1);
            __syncthreads();
            if (warp < OUTC) {
                const float* hrow = g_h[p ^ 1];
                float a = 0.0f;
                for (int k = lane; k < HID; k += 32)
                    a += __ldcg(hrow + k) * outW[(size_t)warp * HID + k];
#pragma unroll
                for (int off = 16; off; off >>= 1)
                    a += __shfl_xor_sync(0xffffffffu, a, off);
                if (lane == 0) s->pred[warp] = a + outb[warp];
            }
            __syncthreads();
            if (tid == 0) {
                for (int o = 0; o < OUTC; o++) out[d * OUTC + o] = s->pred[o];
                if (maxlen * OUTC + d < out_size) out[maxlen * OUTC + d] = 1.0f;
                float r = rintf(s->pred[0]);             // half-to-even like jnp.round
                r = fminf(fmaxf(r, 0.0f), (float)(VOCAB - 1));
                int nid = (int)r;
                s->nid = nid;
                if (nid == EOS_TOK) g_done = 1;
            }
            __syncthreads();
            int nid = s->nid;
            float sc = (nid != PAD_TOK) ? 1.0f : 0.0f;
            for (int k = tid; k < EMB; k += NTH)
                __stcg(&g_cur_emb[k], emb[(size_t)nid * EMB + k] * sc);
            __syncthreads();
            if (tid == 0) st_rel(&g_flag2[0], eh + 1);
        }
        __syncthreads();
    }
}

extern "C" void kernel_launch(void* const* d_in, const int* in_sizes, int n_in,
                              void* d_out, int out_size)
{
    const int*   x    = (const int*)  d_in[0];
    const float* emb  = (const float*)d_in[1];
    const float* eWih = (const float*)d_in[2];
    const float* eWhh = (const float*)d_in[3];
    const float* ebih = (const float*)d_in[4];
    const float* ebhh = (const float*)d_in[5];
    const float* dWih = (const float*)d_in[6];
    const float* dWhh = (const float*)d_in[7];
    const float* dbih = (const float*)d_in[8];
    const float* dbhh = (const float*)d_in[9];
    const float* outW = (const float*)d_in[10];
    const float* outb = (const float*)d_in[11];
    const int*   mlp  = (const int*)  d_in[12];
    int seq = in_sizes[0];

    int smem_bytes = (int)sizeof(SM);
    cudaFuncSetAttribute(seq2seq_kernel,
                         cudaFuncAttributeMaxDynamicSharedMemorySize, smem_bytes);

    seq2seq_kernel<<<NBLK, NTH, smem_bytes>>>(
        x, seq, emb, eWih, eWhh, ebih, ebhh,
        dWih, dWhh, dbih, dbhh, outW, outb, mlp,
        (float*)d_out, out_size);
}

// round 15
// speedup vs baseline: 1.3588x; 1.1723x over previous
#include <cuda_runtime.h>
#include <math.h>

// ---------------- problem constants ----------------
#define PAD_TOK 0
#define SOS_TOK 1
#define EOS_TOK 2
#define VOCAB   50000
#define EMB     512
#define HID     1024
#define OUTC    5

// ---------------- kernel geometry ----------------
#define NBLK   128
#define NTH    256
#define UNITS  8              // warp u owns unit u
#define NJX    8              // x chunks (smem weights)
#define NJH    16             // h chunks (register weights)
#define XWS_ROW 512
#define TOKCAP 2048
#define FSTR   32

typedef unsigned long long u64t;

// ---------------- global state ----------------
__device__ unsigned g_flags[NBLK * FSTR];   // warp-arrival counters: +8 per step
__device__ unsigned g_flag2[FSTR];          // block0 -> all; +1 per event (r9 schema)
__device__ __align__(16) float g_h[2][HID];
__device__ __align__(16) float g_cur_emb[EMB];
__device__ int g_done;

// ---------------- sync primitives (r9-proven forms) ----------------
__device__ __forceinline__ unsigned ld_acq(const unsigned* p) {
    unsigned v;
    asm volatile("ld.acquire.gpu.global.u32 %0, [%1];" : "=r"(v) : "l"(p) : "memory");
    return v;
}
__device__ __forceinline__ void st_rel(unsigned* p, unsigned v) {
    asm volatile("st.release.gpu.global.u32 [%0], %1;" :: "l"(p), "r"(v) : "memory");
}
__device__ __forceinline__ void wait_ge(const unsigned* p, unsigned tgt) {
    while ((int)(ld_acq(p) - tgt) < 0) { }
}
// per-warp publish: release-RMW orders this thread's prior h store before the
// increment; acquire readers of the 8th increment see all 8 warps' stores.
__device__ __forceinline__ void red_rel_add1(unsigned* p) {
    asm volatile("red.release.gpu.global.add.u32 [%0], %1;" :: "l"(p), "r"(1u) : "memory");
}

// ---------------- packed dual-FMA ----------------
__device__ __forceinline__ void fma2(u64t& d, u64t a, u64t b) {
    asm("fma.rn.f32x2 %0, %1, %2, %0;" : "+l"(d) : "l"(a), "l"(b));
}
__device__ __forceinline__ float f2lo(u64t v) { return __uint_as_float((unsigned)v); }
__device__ __forceinline__ float f2hi(u64t v) { return __uint_as_float((unsigned)(v >> 32)); }

__device__ __forceinline__ float fsig(float x)  { return __fdividef(1.0f, 1.0f + __expf(-x)); }
__device__ __forceinline__ float ftanh(float x) { return 1.0f - __fdividef(2.0f, __expf(2.0f * x) + 1.0f); }

// ---------------- smem plan ----------------
struct SM {
    float hbuf[2][HID];        // staged h, double-buffered by parity
    float xbuf[3][EMB];        // staged x, triple-buffered
    float xws[32 * XWS_ROW];   // x weights (64 KB)
    int   x_tok[TOKCAP];
    float pred[OUTC];
    int   nid;
    int   done;
    unsigned sbase;
};

// ---------------- weight load ----------------
__device__ __forceinline__ void load_w(
    const float* __restrict__ Wih, const float* __restrict__ Whh,
    const float* __restrict__ bih, const float* __restrict__ bhh,
    u64t (&wr)[4][NJH], float* xws, float (&bias)[4],
    int b, int u, int lane, int tid)
{
#pragma unroll
    for (int q = 0; q < 4; q++) {
        size_t G = (size_t)q * HID + (size_t)b * UNITS + u;
        const float* rh = Whh + G * HID;
#pragma unroll
        for (int j = 0; j < NJH; j++)
            wr[q][j] = *(const u64t*)(rh + j * 64 + lane * 2);
    }
    for (int i = tid; i < 32 * (XWS_ROW / 4); i += NTH) {
        int r = i >> 7, c = i & 127;
        int q = r >> 3, uu = r & 7;
        size_t G = (size_t)q * HID + (size_t)b * UNITS + uu;
        ((float4*)(xws + (size_t)r * XWS_ROW))[c] = ((const float4*)(Wih + G * EMB))[c];
    }
#pragma unroll
    for (int q = 0; q < 4; q++) {   // all lanes: distributed finish needs bias[lane&3]
        size_t G = (size_t)q * HID + (size_t)b * UNITS + u;
        bias[q] = bih[G] + bhh[G];
    }
}

__device__ __forceinline__ void mac_x(const float* xws, const float* xv,
                                      int u, int lane, u64t (&acc)[4])
{
#pragma unroll
    for (int j = 0; j < NJX; j++) {
        u64t v = *(const u64t*)(xv + j * 64 + lane * 2);
#pragma unroll
        for (int q = 0; q < 4; q++) {
            u64t wv = *(const u64t*)(xws + (size_t)(q * 8 + u) * XWS_ROW
                                         + j * 64 + lane * 2);
            fma2(acc[q], wv, v);
        }
    }
}

__device__ __forceinline__ void mac_h(const u64t (&wr)[4][NJH], const float* hv,
                                      int lane, u64t (&acc)[4])
{
#pragma unroll
    for (int j = 0; j < NJH; j++) {
        u64t v = *(const u64t*)(hv + j * 64 + lane * 2);
        fma2(acc[0], wr[0][j], v);
        fma2(acc[1], wr[1][j], v);
        fma2(acc[2], wr[2][j], v);
        fma2(acc[3], wr[3][j], v);
    }
}

// distributed finish (validated in r12/r14)
__device__ __forceinline__ float finish_unit(u64t (&acc)[4], const float (&bias)[4],
                                             int lane, float& cstate)
{
    float a0 = f2lo(acc[0]) + f2hi(acc[0]);
    float a1 = f2lo(acc[1]) + f2hi(acc[1]);
    float a2 = f2lo(acc[2]) + f2hi(acc[2]);
    float a3 = f2lo(acc[3]) + f2hi(acc[3]);
#pragma unroll
    for (int off = 16; off >= 4; off >>= 1) {
        a0 += __shfl_xor_sync(0xffffffffu, a0, off);
        a1 += __shfl_xor_sync(0xffffffffu, a1, off);
        a2 += __shfl_xor_sync(0xffffffffu, a2, off);
        a3 += __shfl_xor_sync(0xffffffffu, a3, off);
    }
    float t02 = (lane & 2) ? a2 : a0;
    float o02 = (lane & 2) ? a0 : a2;
    t02 += __shfl_xor_sync(0xffffffffu, o02, 2);
    float t13 = (lane & 2) ? a3 : a1;
    float o13 = (lane & 2) ? a1 : a3;
    t13 += __shfl_xor_sync(0xffffffffu, o13, 2);
    float v = (lane & 1) ? t13 : t02;
    float o = (lane & 1) ? t02 : t13;
    v += __shfl_xor_sync(0xffffffffu, o, 1);

    float bsel = (lane & 2) ? ((lane & 1) ? bias[3] : bias[2])
                            : ((lane & 1) ? bias[1] : bias[0]);
    float g = v + bsel;
    bool is_g = ((lane & 3) == 2);
    float m = is_g ? 2.0f : 1.0f;
    float c0 = is_g ? -1.0f : 0.0f;
    float act = fmaf(m, fsig(m * g), c0);

    float si = act;
    float sf = __shfl_sync(0xffffffffu, act, 1);
    float tg = __shfl_sync(0xffffffffu, act, 2);
    float so = __shfl_sync(0xffffffffu, act, 3);
    float hn = 0.0f;
    if (lane == 0) {
        float cn = sf * cstate + si * tg;
        hn = so * ftanh(cn);
        cstate = cn;
    }
    return hn;
}

extern __shared__ __align__(16) unsigned char smem_raw[];

__global__ void __launch_bounds__(NTH, 1)
seq2seq_kernel(const int* __restrict__ x_ids, int seq,
               const float* __restrict__ emb,
               const float* __restrict__ eWih, const float* __restrict__ eWhh,
               const float* __restrict__ ebih, const float* __restrict__ ebhh,
               const float* __restrict__ dWih, const float* __restrict__ dWhh,
               const float* __restrict__ dbih, const float* __restrict__ dbhh,
               const float* __restrict__ outW, const float* __restrict__ outb,
               const int* __restrict__ maxlen_p,
               float* __restrict__ out, int out_size)
{
    SM* s = (SM*)smem_raw;
    const int tid = threadIdx.x;
    const int b = blockIdx.x;
    const int warp = tid >> 5, lane = tid & 31;   // warp == unit u
    const int tid2 = tid - 128;

    // base from OWN flag only (no cross-CTA read -> no init race).
    if (tid == 0) s->sbase = __ldcg(&g_flags[b * FSTR]);

    u64t wr[4][NJH];
    float bias[4];
    load_w(eWih, eWhh, ebih, ebhh, wr, s->xws, bias, b, warp, lane, tid);
    float cstate = 0.0f;
    for (int k = tid; k < seq && k < TOKCAP; k += NTH) s->x_tok[k] = x_ids[k];
    __syncthreads();
    const unsigned B  = s->sbase;        // multiple of 8 (8 per step, all steps complete)
    const unsigned S0 = B >> 3;          // step count base; flag2 ends each replay == S0'

    // publish h_0 = 0 (each warp: store + release increment -> flag B+8)
    if (lane == 0) {
        __stcg(&g_h[0][b * UNITS + warp], 0.0f);
        red_rel_add1(&g_flags[b * FSTR]);
    }
    if (b == 0) {                        // decoder feedback init + flag2 jump-init (r9 schema)
        for (int k = tid; k < out_size; k += NTH) out[k] = 0.0f;
        if (tid < EMB / 4)
            __stcg(((float4*)g_cur_emb) + tid,
                   ((const float4*)(emb + (size_t)SOS_TOK * EMB))[tid]);
        if (tid == 0) g_done = 0;
        __syncthreads();
        if (tid == 0) st_rel(&g_flag2[0], S0 + 1 + (unsigned)seq);
    }

    // bootstrap: xbuf[0] = emb[x_0]; epf = emb[x_1]
    float4 epf = make_float4(0.f, 0.f, 0.f, 0.f);
    if (tid2 >= 0 && seq > 0) {
        int tok0 = s->x_tok[0];
        ((float4*)s->xbuf[0])[tid2] = ((const float4*)(emb + (size_t)tok0 * EMB))[tid2];
        if (seq > 1) {
            int tok1 = s->x_tok[1];
            epf = ((const float4*)(emb + (size_t)tok1 * EMB))[tid2];
        }
    }
    __syncthreads();

    // ---- encoder: ONE sync per step ----
    for (int t = 0; t < seq; t++) {
        u64t acc[4] = {0ull, 0ull, 0ull, 0ull};
        mac_x(s->xws, s->xbuf[t % 3], warp, lane, acc);

        if (tid < 128) {
            wait_ge(&g_flags[tid * FSTR], B + 8u * (unsigned)(t + 1));
            const float4* hp = (const float4*)(g_h[t & 1] + tid * UNITS);
            float4 v0 = __ldcg(hp), v1 = __ldcg(hp + 1);
            ((float4*)(s->hbuf[t & 1]))[tid * 2 + 0] = v0;
            ((float4*)(s->hbuf[t & 1]))[tid * 2 + 1] = v1;
        } else {
            if (t + 1 < seq) ((float4*)s->xbuf[(t + 1) % 3])[tid2] = epf;
            if (t + 2 < seq) {
                int tk = s->x_tok[t + 2];
                epf = ((const float4*)(emb + (size_t)tk * EMB))[tid2];
            }
        }
        __syncthreads();

        mac_h(wr, s->hbuf[t & 1], lane, acc);
        float hn = finish_unit(acc, bias, lane, cstate);
        if (lane == 0) {                 // immediate per-warp publish (no tail sync)
            __stcg(&g_h[(t + 1) & 1][b * UNITS + warp], hn);
            red_rel_add1(&g_flags[b * FSTR]);
        }
    }

    // ---- decoder weights ----
    __syncthreads();
    load_w(dWih, dWhh, dbih, dbhh, wr, s->xws, bias, b, warp, lane, tid);
    const int maxlen = *maxlen_p;
    __syncthreads();

    // ---- decoder: r9 epoch schema, x8 h-flag targets, per-warp publish ----
    for (int d = 0; d < maxlen; d++) {
        if (tid == 0) {
            wait_ge(&g_flag2[0], S0 + 1u + (unsigned)seq + (unsigned)d);
            s->done = __ldcg(&g_done);
        }
        __syncthreads();
        if (s->done) break;

        int p = (seq + d) & 1;
        if (tid < 128) {
            ((float4*)s->xbuf[0])[tid] = __ldcg(((const float4*)g_cur_emb) + tid);
            wait_ge(&g_flags[tid * FSTR], B + 8u * (unsigned)(seq + d + 1));
            const float4* hp = (const float4*)(g_h[p] + tid * UNITS);
            float4 v0 = __ldcg(hp), v1 = __ldcg(hp + 1);
            ((float4*)(s->hbuf[0]))[tid * 2 + 0] = v0;
            ((float4*)(s->hbuf[0]))[tid * 2 + 1] = v1;
        }
        __syncthreads();

        u64t acc[4] = {0ull, 0ull, 0ull, 0ull};
        mac_x(s->xws, s->xbuf[0], warp, lane, acc);
        mac_h(wr, s->hbuf[0], lane, acc);
        float hn = finish_unit(acc, bias, lane, cstate);
        if (lane == 0) {
            __stcg(&g_h[p ^ 1][b * UNITS + warp], hn);
            red_rel_add1(&g_flags[b * FSTR]);
        }

        if (b == 0) {   // projection + greedy feedback
            if (tid < 128) wait_ge(&g_flags[tid * FSTR], B + 8u * (unsigned)(seq + d + 2));
            __syncthreads();
            if (warp < OUTC) {
                const float* hrow = g_h[p ^ 1];
                float a = 0.0f;
                for (int k = lane; k < HID; k += 32)
                    a += __ldcg(hrow + k) * outW[(size_t)warp * HID + k];
#pragma unroll
                for (int off = 16; off; off >>= 1)
                    a += __shfl_xor_sync(0xffffffffu, a, off);
                if (lane == 0) s->pred[warp] = a + outb[warp];
            }
            __syncthreads();
            if (tid == 0) {
                for (int o = 0; o < OUTC; o++) out[d * OUTC + o] = s->pred[o];
                if (maxlen * OUTC + d < out_size) out[maxlen * OUTC + d] = 1.0f;
                float r = rintf(s->pred[0]);         // half-to-even like jnp.round
                r = fminf(fmaxf(r, 0.0f), (float)(VOCAB - 1));
                int nid = (int)r;
                s->nid = nid;
                if (nid == EOS_TOK) g_done = 1;
            }
            __syncthreads();
            int nid = s->nid;
            float sc = (nid != PAD_TOK) ? 1.0f : 0.0f;
            for (int k = tid; k < EMB; k += NTH)
                __stcg(&g_cur_emb[k], emb[(size_t)nid * EMB + k] * sc);
            __syncthreads();
            if (tid == 0) st_rel(&g_flag2[0], S0 + 2u + (unsigned)seq + (unsigned)d);
        }
        __syncthreads();   // decoder buffer (hbuf[0]/xbuf[0]) reuse gate
    }
}

extern "C" void kernel_launch(void* const* d_in, const int* in_sizes, int n_in,
                              void* d_out, int out_size)
{
    const int*   x    = (const int*)  d_in[0];
    const float* emb  = (const float*)d_in[1];
    const float* eWih = (const float*)d_in[2];
    const float* eWhh = (const float*)d_in[3];
    const float* ebih = (const float*)d_in[4];
    const float* ebhh = (const float*)d_in[5];
    const float* dWih = (const float*)d_in[6];
    const float* dWhh = (const float*)d_in[7];
    const float* dbih = (const float*)d_in[8];
    const float* dbhh = (const float*)d_in[9];
    const float* outW = (const float*)d_in[10];
    const float* outb = (const float*)d_in[11];
    const int*   mlp  = (const int*)  d_in[12];
    int seq = in_sizes[0];
    if (seq > TOKCAP) seq = TOKCAP;

    int smem_bytes = (int)sizeof(SM);
    cudaFuncSetAttribute(seq2seq_kernel,
                         cudaFuncAttributeMaxDynamicSharedMemorySize, smem_bytes);
    seq2seq_kernel<<<NBLK, NTH, smem_bytes>>>(
        x, seq, emb, eWih, eWhh, ebih, ebhh,
        dWih, dWhh, dbih, dbhh, outW, outb, mlp,
        (float*)d_out, out_size);
}